// round 9
// baseline (speedup 1.0000x reference)
#include <cuda_runtime.h>

typedef unsigned long long u64;
#define DEV_INLINE __device__ __forceinline__

DEV_INLINE u64 pack2(float lo, float hi) {
    u64 r; asm("mov.b64 %0, {%1,%2};" : "=l"(r) : "f"(lo), "f"(hi)); return r;
}
DEV_INLINE void unpack2(u64 v, float& lo, float& hi) {
    asm("mov.b64 {%0,%1}, %2;" : "=f"(lo), "=f"(hi) : "l"(v));
}
DEV_INLINE u64 fma2(u64 a, u64 b, u64 c) {
    u64 d; asm("fma.rn.f32x2 %0, %1, %2, %3;" : "=l"(d) : "l"(a), "l"(b), "l"(c)); return d;
}

// ---------------- scratch buffers (device globals; no allocation) ----------------
#define B_   16
#define T0_  2048
__device__ float g_h   [B_*64 *T0_];   // conv_in out (= hold)
__device__ float g_xn  [B_*64 *T0_];   // rmsnorm out
__device__ float g_xz  [B_*256*T0_];   // in_proj out: ch 0..127 = xm, 128..255 = z
__device__ float g_xs  [B_*128*T0_];   // dwconv+silu out (u)
__device__ float g_xdbl[B_*36 *T0_];   // x_proj out: 0..3 dt, 4..19 B, 20..35 C
__device__ float g_dl  [B_*128*T0_];   // delta (softplus)
__device__ float g_y   [B_*128*T0_];   // scan out * silu(z)
__device__ float g_h2  [B_*64 *T0_];   // mamba out (+residual)
__device__ float g_mg  [B_*64 *T0_];   // merge conv raw
__device__ float g_m   [B_*64 *T0_];   // post-BN + hold
__device__ float g_u5  [B_*320*10240]; // up1 (shuffled)
__device__ float g_u10 [B_*128*20480]; // up2 (shuffled)
__device__ float g_stats[128];         // mean[64], rstd[64]

// ---------------- generic conv1d (cross-correlation), FFMA2 register-blocked ----
constexpr int A_NONE = 0, A_LEAKY = 1, A_SOFTPLUS = 2;

template<int K, int PAD, int CG, int CPT, int TG, int R, int ACT, bool HAS_BIAS, bool HAS_RES>
__global__ void __launch_bounds__(CG*TG)
conv_kern(const float* __restrict__ in, const float* __restrict__ w,
          const float* __restrict__ bias, const float* __restrict__ res,
          float* __restrict__ out, int CI, int CO, int T, int inbs)
{
    constexpr int TT      = 8;
    constexpr int T_TILE  = TG * TT;
    constexpr int CO_TILE = CG * CPT;
    constexpr int NT      = CG * TG;
    constexpr int XN      = T_TILE + K - 1;
    constexpr int XNP     = (XN + 3) & ~3;
    constexpr int WN      = CO_TILE * K;
    constexpr int XE      = (XN + NT - 1) / NT;
    constexpr int WE      = (WN + NT - 1) / NT;

    __shared__ __align__(16) float  sx[2][XNP];
    __shared__ float2               sw[2][WN];

    const int tid = threadIdx.x;
    const int tg  = tid % TG;
    const int cg  = tid / TG;
    const int b   = blockIdx.z;
    const int t0  = blockIdx.x * T_TILE;
    const int co0 = blockIdx.y * CO_TILE;
    const float* inb = in + (long)b * inbs;

    float rx[XE], rw[WE];
    auto prefetch = [&](int ci) {
#pragma unroll
        for (int e = 0; e < XE; e++) {
            int idx = tid + e * NT;
            if (idx < XN) {
                int gt = t0 - PAD + idx;
                rx[e] = (gt >= 0 && gt < T) ? __ldg(inb + (long)ci * T + gt) : 0.f;
            }
        }
#pragma unroll
        for (int e = 0; e < WE; e++) {
            int idx = tid + e * NT;
            if (idx < WN) {
                int co = idx / K, k = idx % K;
                int gco = co0 + co;
                rw[e] = (gco < CO) ? __ldg(w + ((long)gco * CI + ci) * K + k) : 0.f;
            }
        }
    };
    auto store_buf = [&](int bf) {
#pragma unroll
        for (int e = 0; e < XE; e++) {
            int idx = tid + e * NT;
            if (idx < XN) sx[bf][idx] = rx[e];
        }
#pragma unroll
        for (int e = 0; e < WE; e++) {
            int idx = tid + e * NT;
            if (idx < WN) sw[bf][idx] = make_float2(rw[e], rw[e]);
        }
    };

    u64 acc[CPT][TT/2];
#pragma unroll
    for (int i = 0; i < CPT; i++) {
        int co = co0 + cg * CPT + i;
        float bv = (HAS_BIAS && co < CO) ? __ldg(bias + co) : 0.f;
        u64 p = pack2(bv, bv);
#pragma unroll
        for (int j = 0; j < TT/2; j++) acc[i][j] = p;
    }

    prefetch(0);
    store_buf(0);
    int bf = 0;
    for (int ci = 0; ci < CI; ci++) {
        __syncthreads();
        if (ci + 1 < CI) prefetch(ci + 1);

        float xr[TT + K - 1];
        const float* xp_ = &sx[bf][tg * TT];
#pragma unroll
        for (int i = 0; i < TT + K - 1; i++) xr[i] = xp_[i];
        const u64* swb = (const u64*)&sw[bf][0];
#pragma unroll
        for (int k = 0; k < K; k++) {
            u64 xv[TT/2];
#pragma unroll
            for (int j = 0; j < TT/2; j++) xv[j] = pack2(xr[k + 2*j], xr[k + 2*j + 1]);
#pragma unroll
            for (int i = 0; i < CPT; i++) {
                u64 wd = swb[(cg * CPT + i) * K + k];
#pragma unroll
                for (int j = 0; j < TT/2; j++) acc[i][j] = fma2(wd, xv[j], acc[i][j]);
            }
        }
        if (ci + 1 < CI) store_buf(bf ^ 1);
        bf ^= 1;
    }

    // epilogue: activation, optional residual, optional pixel-shuffle store
#pragma unroll
    for (int i = 0; i < CPT; i++) {
        int co = co0 + cg * CPT + i;
        if (co >= CO) continue;
#pragma unroll
        for (int j = 0; j < TT/2; j++) {
            float v0, v1; unpack2(acc[i][j], v0, v1);
            if (ACT == A_LEAKY) {
                v0 = v0 >= 0.f ? v0 : 0.01f * v0;
                v1 = v1 >= 0.f ? v1 : 0.01f * v1;
            } else if (ACT == A_SOFTPLUS) {
                v0 = v0 > 20.f ? v0 : log1pf(__expf(v0));
                v1 = v1 > 20.f ? v1 : log1pf(__expf(v1));
            }
            int t = t0 + tg * TT + 2 * j;
            if (R == 1) {
                long o = ((long)b * CO + co) * T + t;
                if (HAS_RES) { v0 += res[o]; v1 += res[o + 1]; }
                out[o] = v0; out[o + 1] = v1;
            } else {
                int  C2 = CO / R;
                long T2 = (long)T * R;
                long o  = ((long)b * C2 + co / R) * T2 + (long)t * R + (co % R);
                out[o] = v0; out[o + R] = v1;
            }
        }
    }
}

// ---------------- rmsnorm over channel dim (64), layout (b,64,T) ----------------
__global__ void rms_kern(const float* __restrict__ x, const float* __restrict__ nw,
                         float* __restrict__ xn, int T)
{
    int b = blockIdx.y;
    int t = blockIdx.x * blockDim.x + threadIdx.x;
    const float* p = x + (long)b * 64 * T + t;
    float s = 0.f;
#pragma unroll
    for (int c = 0; c < 64; c++) { float v = p[(long)c * T]; s += v * v; }
    float r = rsqrtf(s * (1.f / 64.f) + 1e-5f);
    float* q = xn + (long)b * 64 * T + t;
#pragma unroll
    for (int c = 0; c < 64; c++) q[(long)c * T] = p[(long)c * T] * r * __ldg(nw + c);
}

// ---------------- causal depthwise conv (k=4) + silu ----------------------------
__global__ void dwconv_kern(const float* __restrict__ xz, const float* __restrict__ w,
                            const float* __restrict__ bias, float* __restrict__ xs, int T)
{
    int b = blockIdx.y;
    int d = threadIdx.x;              // 128
    int t0 = blockIdx.x * 128;
    const float* x = xz + ((long)b * 256 + d) * T;   // xm = channels 0..127
    float w0 = w[d*4+0], w1 = w[d*4+1], w2 = w[d*4+2], w3 = w[d*4+3], bb = bias[d];
    float a  = (t0 >= 3) ? x[t0-3] : 0.f;
    float c1 = (t0 >= 2) ? x[t0-2] : 0.f;
    float c2 = (t0 >= 1) ? x[t0-1] : 0.f;
    float* o = xs + ((long)b * 128 + d) * T;
    for (int i = 0; i < 128; i++) {
        float c3 = x[t0 + i];
        float v  = w0*a + w1*c1 + w2*c2 + w3*c3 + bb;
        o[t0 + i] = v * (1.f / (1.f + __expf(-v)));   // silu
        a = c1; c1 = c2; c2 = c3;
    }
}

// ---------------- selective scan (sequential over T), 1 block per batch ---------
__global__ void scan_kern(const float* __restrict__ u_, const float* __restrict__ dl_,
                          const float* __restrict__ xz, const float* __restrict__ xdbl,
                          const float* __restrict__ A_log, const float* __restrict__ Dv,
                          float* __restrict__ yout, int T)
{
    int b = blockIdx.x;
    int d = threadIdx.x;              // 128
    float A[16];
#pragma unroll
    for (int n = 0; n < 16; n++) A[n] = -expf(__ldg(A_log + d * 16 + n));
    float Dd = __ldg(Dv + d);
    const float* u  = u_  + ((long)b * 128 + d) * T;
    const float* dl = dl_ + ((long)b * 128 + d) * T;
    const float* z  = xz  + ((long)b * 256 + 128 + d) * T;
    const float* Bc = xdbl + ((long)b * 36 + 4)  * T;
    const float* Cc = xdbl + ((long)b * 36 + 20) * T;
    float* y = yout + ((long)b * 128 + d) * T;

    float h[16];
#pragma unroll
    for (int n = 0; n < 16; n++) h[n] = 0.f;

    for (int t = 0; t < T; t++) {
        float dt = dl[t], ut = u[t];
        float du = dt * ut;
        float acc = 0.f;
#pragma unroll
        for (int n = 0; n < 16; n++) {
            float dA = __expf(dt * A[n]);
            h[n] = h[n] * dA + du * __ldg(Bc + (long)n * T + t);
            acc += h[n] * __ldg(Cc + (long)n * T + t);
        }
        float yt = acc + ut * Dd;
        float zt = z[t];
        y[t] = yt * (zt * (1.f / (1.f + __expf(-zt))));
    }
}

// ---------------- batchnorm: training-mode stats + apply(+hold) -----------------
__global__ void bnstat_kern(const float* __restrict__ x, float* __restrict__ stats, int T)
{
    int c = blockIdx.x, tid = threadIdx.x;
    int N = 16 * T;
    float s = 0.f, s2 = 0.f;
    for (int i = tid; i < N; i += 256) {
        int b = i / T, t = i - b * T;
        float v = x[((long)b * 64 + c) * T + t];
        s += v; s2 += v * v;
    }
    __shared__ float rs[256], rq[256];
    rs[tid] = s; rq[tid] = s2;
    __syncthreads();
    for (int st = 128; st > 0; st >>= 1) {
        if (tid < st) { rs[tid] += rs[tid + st]; rq[tid] += rq[tid + st]; }
        __syncthreads();
    }
    if (tid == 0) {
        float mean = rs[0] / N;
        float var  = rq[0] / N - mean * mean;
        stats[c] = mean;
        stats[64 + c] = rsqrtf(var + 1e-5f);
    }
}

__global__ void bnapply_kern(const float* __restrict__ x, const float* __restrict__ stats,
                             const float* __restrict__ g, const float* __restrict__ bb,
                             const float* __restrict__ hold, float* __restrict__ m, int T)
{
    long idx = (long)blockIdx.x * blockDim.x + threadIdx.x;
    long tot = (long)16 * 64 * T;
    if (idx >= tot) return;
    int c = (int)((idx / T) % 64);
    m[idx] = (x[idx] - stats[c]) * stats[64 + c] * g[c] + bb[c] + hold[idx];
}

// ---------------- launch --------------------------------------------------------
extern "C" void kernel_launch(void* const* d_in, const int* in_sizes, int n_in,
                              void* d_out, int out_size)
{
    (void)in_sizes; (void)n_in; (void)out_size;
    const float* x         = (const float*)d_in[0];
    const float* conv_in_w = (const float*)d_in[1];
    const float* conv_in_b = (const float*)d_in[2];
    const float* norm_w    = (const float*)d_in[3];
    const float* in_proj_w = (const float*)d_in[4];
    const float* dwconv_w  = (const float*)d_in[5];
    const float* dwconv_b  = (const float*)d_in[6];
    const float* x_proj_w  = (const float*)d_in[7];
    const float* dt_proj_w = (const float*)d_in[8];
    const float* dt_proj_b = (const float*)d_in[9];
    const float* A_log     = (const float*)d_in[10];
    const float* Dv        = (const float*)d_in[11];
    const float* out_proj_w= (const float*)d_in[12];
    const float* merge_w   = (const float*)d_in[13];
    const float* merge_b   = (const float*)d_in[14];
    const float* bn_g      = (const float*)d_in[15];
    const float* bn_b      = (const float*)d_in[16];
    const float* up1_w     = (const float*)d_in[17];
    const float* up1_b     = (const float*)d_in[18];
    const float* up2_w     = (const float*)d_in[19];
    const float* up2_b     = (const float*)d_in[20];
    const float* out_w     = (const float*)d_in[21];
    const float* out_b     = (const float*)d_in[22];
    float* dout = (float*)d_out;

    float *ph, *pxn, *pxz, *pxs, *pxdbl, *pdl, *py, *ph2, *pmg, *pm, *pu5, *pu10, *pst;
    cudaGetSymbolAddress((void**)&ph,    g_h);
    cudaGetSymbolAddress((void**)&pxn,   g_xn);
    cudaGetSymbolAddress((void**)&pxz,   g_xz);
    cudaGetSymbolAddress((void**)&pxs,   g_xs);
    cudaGetSymbolAddress((void**)&pxdbl, g_xdbl);
    cudaGetSymbolAddress((void**)&pdl,   g_dl);
    cudaGetSymbolAddress((void**)&py,    g_y);
    cudaGetSymbolAddress((void**)&ph2,   g_h2);
    cudaGetSymbolAddress((void**)&pmg,   g_mg);
    cudaGetSymbolAddress((void**)&pm,    g_m);
    cudaGetSymbolAddress((void**)&pu5,   g_u5);
    cudaGetSymbolAddress((void**)&pu10,  g_u10);
    cudaGetSymbolAddress((void**)&pst,   g_stats);

    const int T = 2048;

    // 1. conv_in (12->64, k=15, pad 7) + leaky
    conv_kern<15,7,8,8,32,1,A_LEAKY,true,false>
        <<<dim3(8,1,16),256>>>(x, conv_in_w, conv_in_b, nullptr, ph, 12, 64, T, 12*T);
    // 2. rmsnorm
    rms_kern<<<dim3(T/256,16),256>>>(ph, norm_w, pxn, T);
    // 3. in_proj (64->256, k=1, no bias)
    conv_kern<1,0,8,8,32,1,A_NONE,false,false>
        <<<dim3(8,4,16),256>>>(pxn, in_proj_w, nullptr, nullptr, pxz, 64, 256, T, 64*T);
    // 4. depthwise causal conv + silu
    dwconv_kern<<<dim3(T/128,16),128>>>(pxz, dwconv_w, dwconv_b, pxs, T);
    // 5. x_proj (128->36, k=1, no bias)
    conv_kern<1,0,9,4,32,1,A_NONE,false,false>
        <<<dim3(8,1,16),288>>>(pxs, x_proj_w, nullptr, nullptr, pxdbl, 128, 36, T, 128*T);
    // 6. delta = softplus(dt @ dt_proj_w.T + b)  (4->128, k=1; input = dt rows of xdbl)
    conv_kern<1,0,16,8,32,1,A_SOFTPLUS,true,false>
        <<<dim3(8,1,16),512>>>(pxdbl, dt_proj_w, dt_proj_b, nullptr, pdl, 4, 128, T, 36*T);
    // 7. selective scan (+ D skip + silu(z) gate)
    scan_kern<<<16,128>>>(pxs, pdl, pxz, pxdbl, A_log, Dv, py, T);
    // 8. out_proj (128->64, k=1, no bias) + residual h
    conv_kern<1,0,8,8,32,1,A_NONE,false,true>
        <<<dim3(8,1,16),256>>>(py, out_proj_w, nullptr, ph, ph2, 128, 64, T, 128*T);
    // 9. merge conv (64->64, k=15, pad 7)
    conv_kern<15,7,8,8,32,1,A_NONE,true,false>
        <<<dim3(8,1,16),256>>>(ph2, merge_w, merge_b, nullptr, pmg, 64, 64, T, 64*T);
    // 10-11. batchnorm (training stats) + hold residual
    bnstat_kern<<<64,256>>>(pmg, pst, T);
    bnapply_kern<<<(16*64*T + 255)/256,256>>>(pmg, pst, bn_g, bn_b, ph, pm, T);
    // 12. up1 (64->1600, k=15) + pixel_shuffle r=5 + leaky -> (b,320,10240)
    conv_kern<15,7,8,8,32,5,A_LEAKY,true,false>
        <<<dim3(8,25,16),256>>>(pm, up1_w, up1_b, nullptr, pu5, 64, 1600, T, 64*T);
    // 13. up2 (320->256, k=15) + pixel_shuffle r=2 + leaky -> (b,128,20480)
    conv_kern<15,7,8,8,32,2,A_LEAKY,true,false>
        <<<dim3(40,4,16),256>>>(pu5, up2_w, up2_b, nullptr, pu10, 320, 256, 10240, 320*10240);
    // 14. out conv (128->12, k=15) -> d_out
    conv_kern<15,7,6,2,32,1,A_NONE,true,false>
        <<<dim3(80,1,16),192>>>(pu10, out_w, out_b, nullptr, dout, 128, 12, 20480, 128*20480);
}

// round 10
// speedup vs baseline: 1.2933x; 1.2933x over previous
#include <cuda_runtime.h>

typedef unsigned long long u64;
#define DEV_INLINE __device__ __forceinline__

DEV_INLINE u64 pack2(float lo, float hi) {
    u64 r; asm("mov.b64 %0, {%1,%2};" : "=l"(r) : "f"(lo), "f"(hi)); return r;
}
DEV_INLINE void unpack2(u64 v, float& lo, float& hi) {
    asm("mov.b64 {%0,%1}, %2;" : "=f"(lo), "=f"(hi) : "l"(v));
}
DEV_INLINE u64 fma2(u64 a, u64 b, u64 c) {
    u64 d; asm("fma.rn.f32x2 %0, %1, %2, %3;" : "=l"(d) : "l"(a), "l"(b), "l"(c)); return d;
}

// ---------------- scratch buffers (device globals; no allocation) ----------------
#define B_   16
#define T0_  2048
__device__ float g_h   [B_*64 *T0_];   // conv_in out (= hold)
__device__ float g_xn  [B_*64 *T0_];   // rmsnorm out
__device__ float g_xz  [B_*256*T0_];   // in_proj out: ch 0..127 = xm, 128..255 = z
__device__ float g_xs  [B_*128*T0_];   // dwconv+silu out (u)
__device__ float g_xdbl[B_*36 *T0_];   // x_proj out: 0..3 dt, 4..19 B, 20..35 C
__device__ float g_dl  [B_*128*T0_];   // delta (softplus)
__device__ float g_y   [B_*128*T0_];   // scan out * silu(z)
__device__ float g_h2  [B_*64 *T0_];   // mamba out (+residual)
__device__ float g_mg  [B_*64 *T0_];   // merge conv raw
__device__ float g_m   [B_*64 *T0_];   // post-BN + hold
__device__ float g_u5  [B_*320*10240]; // up1 (shuffled)
__device__ float g_u10 [B_*128*20480]; // up2 (shuffled)
__device__ float g_stats[128];         // mean[64], rstd[64]

// ---------------- generic conv1d (cross-correlation), FFMA2, conflict-free ------
// Thread tg=lane owns 4 t-pairs at t_local = lane*2 + j*64 (T_TILE=256).
// x tile kept in TWO smem copies: sx0[i]=x[i], sx1[i]=x[i+1], so any pair
// (x[s],x[s+1]) is ONE aligned LDS.64 (from sx0 if s even, sx1 if s odd).
constexpr int A_NONE = 0, A_LEAKY = 1, A_SOFTPLUS = 2;

template<int K, int PAD, int CG, int CPT, int R, int ACT, bool HAS_BIAS, bool HAS_RES, int MINB>
__global__ void __launch_bounds__(CG*32, MINB)
conv_kern(const float* __restrict__ in, const float* __restrict__ w,
          const float* __restrict__ bias, const float* __restrict__ res,
          float* __restrict__ out, int CI, int CO, int T, int inbs)
{
    constexpr int T_TILE  = 256;
    constexpr int CO_TILE = CG * CPT;
    constexpr int NT      = CG * 32;
    constexpr int XN      = T_TILE + K - 1;
    constexpr int XNP     = (XN + 4 + 3) & ~3;
    constexpr int WN      = CO_TILE * K;
    constexpr int XE      = (XN + NT - 1) / NT;
    constexpr int WE      = (WN + NT - 1) / NT;

    __shared__ __align__(16) float  sx0[2][XNP];
    __shared__ __align__(16) float  sx1[2][XNP];
    __shared__ __align__(16) float2 sw [2][WN];

    const int tid  = threadIdx.x;
    const int lane = tid & 31;
    const int cg   = tid >> 5;
    const int b    = blockIdx.z;
    const int t0   = blockIdx.x * T_TILE;
    const int co0  = blockIdx.y * CO_TILE;
    const float* inb = in + (long)b * inbs;

    float rx[XE], rw[WE];
    auto prefetch = [&](int ci) {
#pragma unroll
        for (int e = 0; e < XE; e++) {
            int idx = tid + e * NT;
            if (idx < XN) {
                int gt = t0 - PAD + idx;
                rx[e] = (gt >= 0 && gt < T) ? __ldg(inb + (long)ci * T + gt) : 0.f;
            }
        }
#pragma unroll
        for (int e = 0; e < WE; e++) {
            int idx = tid + e * NT;
            if (idx < WN) {
                int co = idx / K, k = idx % K;
                int gco = co0 + co;
                rw[e] = (gco < CO) ? __ldg(w + ((long)gco * CI + ci) * K + k) : 0.f;
            }
        }
    };
    auto store_buf = [&](int bf) {
#pragma unroll
        for (int e = 0; e < XE; e++) {
            int idx = tid + e * NT;
            if (idx < XN) {
                float v = rx[e];
                sx0[bf][idx] = v;
                if (idx > 0) sx1[bf][idx - 1] = v;
            }
        }
#pragma unroll
        for (int e = 0; e < WE; e++) {
            int idx = tid + e * NT;
            if (idx < WN) sw[bf][idx] = make_float2(rw[e], rw[e]);
        }
    };

    u64 acc[CPT][4];
#pragma unroll
    for (int i = 0; i < CPT; i++) {
        int co = co0 + cg * CPT + i;
        float bv = (HAS_BIAS && co < CO) ? __ldg(bias + co) : 0.f;
        u64 p = pack2(bv, bv);
#pragma unroll
        for (int j = 0; j < 4; j++) acc[i][j] = p;
    }

    prefetch(0);
    store_buf(0);
    int bf = 0;
    for (int ci = 0; ci < CI; ci++) {
        __syncthreads();
        if (ci + 1 < CI) prefetch(ci + 1);

        const float2* swb = &sw[bf][cg * CPT * K];
#pragma unroll
        for (int k = 0; k < K; k++) {
            const float* xb = (k & 1) ? &sx1[bf][lane * 2 + k - 1]
                                      : &sx0[bf][lane * 2 + k];
            u64 xv[4];
#pragma unroll
            for (int j = 0; j < 4; j++)
                xv[j] = *(const u64*)(xb + j * 64);
#pragma unroll
            for (int i = 0; i < CPT; i++) {
                u64 wd = *(const u64*)(swb + i * K + k);
#pragma unroll
                for (int j = 0; j < 4; j++) acc[i][j] = fma2(wd, xv[j], acc[i][j]);
            }
        }
        if (ci + 1 < CI) store_buf(bf ^ 1);
        bf ^= 1;
    }

    // epilogue: activation, optional residual, optional pixel-shuffle store
#pragma unroll
    for (int i = 0; i < CPT; i++) {
        int co = co0 + cg * CPT + i;
        if (co >= CO) continue;
#pragma unroll
        for (int j = 0; j < 4; j++) {
            float v0, v1; unpack2(acc[i][j], v0, v1);
            if (ACT == A_LEAKY) {
                v0 = v0 >= 0.f ? v0 : 0.01f * v0;
                v1 = v1 >= 0.f ? v1 : 0.01f * v1;
            } else if (ACT == A_SOFTPLUS) {
                v0 = v0 > 20.f ? v0 : log1pf(__expf(v0));
                v1 = v1 > 20.f ? v1 : log1pf(__expf(v1));
            }
            int t = t0 + lane * 2 + j * 64;
            if (R == 1) {
                long o = ((long)b * CO + co) * T + t;
                if (HAS_RES) {
                    float2 rv = *(const float2*)(res + o);
                    v0 += rv.x; v1 += rv.y;
                }
                *(float2*)(out + o) = make_float2(v0, v1);
            } else {
                int  C2 = CO / R;
                long T2 = (long)T * R;
                long o  = ((long)b * C2 + co / R) * T2 + (long)t * R + (co % R);
                out[o] = v0; out[o + R] = v1;
            }
        }
    }
}

// ---------------- rmsnorm over channel dim (64), layout (b,64,T) ----------------
__global__ void rms_kern(const float* __restrict__ x, const float* __restrict__ nw,
                         float* __restrict__ xn, int T)
{
    int b = blockIdx.y;
    int t = blockIdx.x * blockDim.x + threadIdx.x;
    const float* p = x + (long)b * 64 * T + t;
    float s = 0.f;
#pragma unroll
    for (int c = 0; c < 64; c++) { float v = p[(long)c * T]; s += v * v; }
    float r = rsqrtf(s * (1.f / 64.f) + 1e-5f);
    float* q = xn + (long)b * 64 * T + t;
#pragma unroll
    for (int c = 0; c < 64; c++) q[(long)c * T] = p[(long)c * T] * r * __ldg(nw + c);
}

// ---------------- causal depthwise conv (k=4) + silu ----------------------------
__global__ void dwconv_kern(const float* __restrict__ xz, const float* __restrict__ w,
                            const float* __restrict__ bias, float* __restrict__ xs, int T)
{
    int b = blockIdx.y;
    int d = threadIdx.x;              // 128
    int t0 = blockIdx.x * 32;
    const float* x = xz + ((long)b * 256 + d) * T;   // xm = channels 0..127
    float w0 = w[d*4+0], w1 = w[d*4+1], w2 = w[d*4+2], w3 = w[d*4+3], bb = bias[d];
    float a  = (t0 >= 3) ? x[t0-3] : 0.f;
    float c1 = (t0 >= 2) ? x[t0-2] : 0.f;
    float c2 = (t0 >= 1) ? x[t0-1] : 0.f;
    float* o = xs + ((long)b * 128 + d) * T;
#pragma unroll
    for (int i = 0; i < 32; i++) {
        float c3 = x[t0 + i];
        float v  = w0*a + w1*c1 + w2*c2 + w3*c3 + bb;
        o[t0 + i] = v * (1.f / (1.f + __expf(-v)));   // silu
        a = c1; c1 = c2; c2 = c3;
    }
}

// ---------------- selective scan (sequential over T), 1 block per batch ---------
__global__ void scan_kern(const float* __restrict__ u_, const float* __restrict__ dl_,
                          const float* __restrict__ xz, const float* __restrict__ xdbl,
                          const float* __restrict__ A_log, const float* __restrict__ Dv,
                          float* __restrict__ yout, int T)
{
    int b = blockIdx.x;
    int d = threadIdx.x;              // 128
    float A[16];
#pragma unroll
    for (int n = 0; n < 16; n++) A[n] = -expf(__ldg(A_log + d * 16 + n));
    float Dd = __ldg(Dv + d);
    const float* u  = u_  + ((long)b * 128 + d) * T;
    const float* dl = dl_ + ((long)b * 128 + d) * T;
    const float* z  = xz  + ((long)b * 256 + 128 + d) * T;
    const float* Bc = xdbl + ((long)b * 36 + 4)  * T;
    const float* Cc = xdbl + ((long)b * 36 + 20) * T;
    float* y = yout + ((long)b * 128 + d) * T;

    float h[16];
#pragma unroll
    for (int n = 0; n < 16; n++) h[n] = 0.f;

    for (int t = 0; t < T; t++) {
        float dt = dl[t], ut = u[t];
        float du = dt * ut;
        float acc = 0.f;
#pragma unroll
        for (int n = 0; n < 16; n++) {
            float dA = __expf(dt * A[n]);
            h[n] = h[n] * dA + du * __ldg(Bc + (long)n * T + t);
            acc += h[n] * __ldg(Cc + (long)n * T + t);
        }
        float yt = acc + ut * Dd;
        float zt = z[t];
        y[t] = yt * (zt * (1.f / (1.f + __expf(-zt))));
    }
}

// ---------------- batchnorm: training-mode stats + apply(+hold) -----------------
__global__ void bnstat_kern(const float* __restrict__ x, float* __restrict__ stats, int T)
{
    int c = blockIdx.x, tid = threadIdx.x;
    int N = 16 * T;
    float s = 0.f, s2 = 0.f;
    for (int i = tid; i < N; i += 256) {
        int b = i / T, t = i - b * T;
        float v = x[((long)b * 64 + c) * T + t];
        s += v; s2 += v * v;
    }
    __shared__ float rs[256], rq[256];
    rs[tid] = s; rq[tid] = s2;
    __syncthreads();
    for (int st = 128; st > 0; st >>= 1) {
        if (tid < st) { rs[tid] += rs[tid + st]; rq[tid] += rq[tid + st]; }
        __syncthreads();
    }
    if (tid == 0) {
        float mean = rs[0] / N;
        float var  = rq[0] / N - mean * mean;
        stats[c] = mean;
        stats[64 + c] = rsqrtf(var + 1e-5f);
    }
}

__global__ void bnapply_kern(const float* __restrict__ x, const float* __restrict__ stats,
                             const float* __restrict__ g, const float* __restrict__ bb,
                             const float* __restrict__ hold, float* __restrict__ m, int T)
{
    long idx = (long)blockIdx.x * blockDim.x + threadIdx.x;
    long tot = (long)16 * 64 * T;
    if (idx >= tot) return;
    int c = (int)((idx / T) % 64);
    m[idx] = (x[idx] - stats[c]) * stats[64 + c] * g[c] + bb[c] + hold[idx];
}

// ---------------- launch --------------------------------------------------------
extern "C" void kernel_launch(void* const* d_in, const int* in_sizes, int n_in,
                              void* d_out, int out_size)
{
    (void)in_sizes; (void)n_in; (void)out_size;
    const float* x         = (const float*)d_in[0];
    const float* conv_in_w = (const float*)d_in[1];
    const float* conv_in_b = (const float*)d_in[2];
    const float* norm_w    = (const float*)d_in[3];
    const float* in_proj_w = (const float*)d_in[4];
    const float* dwconv_w  = (const float*)d_in[5];
    const float* dwconv_b  = (const float*)d_in[6];
    const float* x_proj_w  = (const float*)d_in[7];
    const float* dt_proj_w = (const float*)d_in[8];
    const float* dt_proj_b = (const float*)d_in[9];
    const float* A_log     = (const float*)d_in[10];
    const float* Dv        = (const float*)d_in[11];
    const float* out_proj_w= (const float*)d_in[12];
    const float* merge_w   = (const float*)d_in[13];
    const float* merge_b   = (const float*)d_in[14];
    const float* bn_g      = (const float*)d_in[15];
    const float* bn_b      = (const float*)d_in[16];
    const float* up1_w     = (const float*)d_in[17];
    const float* up1_b     = (const float*)d_in[18];
    const float* up2_w     = (const float*)d_in[19];
    const float* up2_b     = (const float*)d_in[20];
    const float* out_w     = (const float*)d_in[21];
    const float* out_b     = (const float*)d_in[22];
    float* dout = (float*)d_out;

    float *ph, *pxn, *pxz, *pxs, *pxdbl, *pdl, *py, *ph2, *pmg, *pm, *pu5, *pu10, *pst;
    cudaGetSymbolAddress((void**)&ph,    g_h);
    cudaGetSymbolAddress((void**)&pxn,   g_xn);
    cudaGetSymbolAddress((void**)&pxz,   g_xz);
    cudaGetSymbolAddress((void**)&pxs,   g_xs);
    cudaGetSymbolAddress((void**)&pxdbl, g_xdbl);
    cudaGetSymbolAddress((void**)&pdl,   g_dl);
    cudaGetSymbolAddress((void**)&py,    g_y);
    cudaGetSymbolAddress((void**)&ph2,   g_h2);
    cudaGetSymbolAddress((void**)&pmg,   g_mg);
    cudaGetSymbolAddress((void**)&pm,    g_m);
    cudaGetSymbolAddress((void**)&pu5,   g_u5);
    cudaGetSymbolAddress((void**)&pu10,  g_u10);
    cudaGetSymbolAddress((void**)&pst,   g_stats);

    const int T = 2048;

    // 1. conv_in (12->64, k=15, pad 7) + leaky
    conv_kern<15,7,8,8,1,A_LEAKY,true,false,2>
        <<<dim3(8,1,16),256>>>(x, conv_in_w, conv_in_b, nullptr, ph, 12, 64, T, 12*T);
    // 2. rmsnorm
    rms_kern<<<dim3(T/256,16),256>>>(ph, norm_w, pxn, T);
    // 3. in_proj (64->256, k=1, no bias)
    conv_kern<1,0,8,8,1,A_NONE,false,false,2>
        <<<dim3(8,4,16),256>>>(pxn, in_proj_w, nullptr, nullptr, pxz, 64, 256, T, 64*T);
    // 4. depthwise causal conv + silu
    dwconv_kern<<<dim3(T/32,16),128>>>(pxz, dwconv_w, dwconv_b, pxs, T);
    // 5. x_proj (128->36, k=1, no bias)
    conv_kern<1,0,9,4,1,A_NONE,false,false,2>
        <<<dim3(8,1,16),288>>>(pxs, x_proj_w, nullptr, nullptr, pxdbl, 128, 36, T, 128*T);
    // 6. delta = softplus(dt @ dt_proj_w.T + b)  (4->128, k=1; input = dt rows of xdbl)
    conv_kern<1,0,16,8,1,A_SOFTPLUS,true,false,1>
        <<<dim3(8,1,16),512>>>(pxdbl, dt_proj_w, dt_proj_b, nullptr, pdl, 4, 128, T, 36*T);
    // 7. selective scan (+ D skip + silu(z) gate)
    scan_kern<<<16,128>>>(pxs, pdl, pxz, pxdbl, A_log, Dv, py, T);
    // 8. out_proj (128->64, k=1, no bias) + residual h
    conv_kern<1,0,8,8,1,A_NONE,false,true,2>
        <<<dim3(8,1,16),256>>>(py, out_proj_w, nullptr, ph, ph2, 128, 64, T, 128*T);
    // 9. merge conv (64->64, k=15, pad 7)
    conv_kern<15,7,8,8,1,A_NONE,true,false,2>
        <<<dim3(8,1,16),256>>>(ph2, merge_w, merge_b, nullptr, pmg, 64, 64, T, 64*T);
    // 10-11. batchnorm (training stats) + hold residual
    bnstat_kern<<<64,256>>>(pmg, pst, T);
    bnapply_kern<<<(16*64*T + 255)/256,256>>>(pmg, pst, bn_g, bn_b, ph, pm, T);
    // 12. up1 (64->1600, k=15) + pixel_shuffle r=5 + leaky -> (b,320,10240)
    conv_kern<15,7,8,8,5,A_LEAKY,true,false,2>
        <<<dim3(8,25,16),256>>>(pm, up1_w, up1_b, nullptr, pu5, 64, 1600, T, 64*T);
    // 13. up2 (320->256, k=15) + pixel_shuffle r=2 + leaky -> (b,128,20480)
    conv_kern<15,7,8,8,2,A_LEAKY,true,false,2>
        <<<dim3(40,4,16),256>>>(pu5, up2_w, up2_b, nullptr, pu10, 320, 256, 10240, 320*10240);
    // 14. out conv (128->12, k=15) -> d_out
    conv_kern<15,7,6,2,1,A_NONE,true,false,2>
        <<<dim3(80,1,16),192>>>(pu10, out_w, out_b, nullptr, dout, 128, 12, 20480, 128*20480);
}

// round 12
// speedup vs baseline: 1.3349x; 1.0322x over previous
#include <cuda_runtime.h>

typedef unsigned long long u64;
#define DEV_INLINE __device__ __forceinline__

DEV_INLINE u64 pack2(float lo, float hi) {
    u64 r; asm("mov.b64 %0, {%1,%2};" : "=l"(r) : "f"(lo), "f"(hi)); return r;
}
DEV_INLINE void unpack2(u64 v, float& lo, float& hi) {
    asm("mov.b64 {%0,%1}, %2;" : "=f"(lo), "=f"(hi) : "l"(v));
}
DEV_INLINE u64 fma2(u64 a, u64 b, u64 c) {
    u64 d; asm("fma.rn.f32x2 %0, %1, %2, %3;" : "=l"(d) : "l"(a), "l"(b), "l"(c)); return d;
}

// ---------------- scratch buffers (device globals; no allocation) ----------------
#define B_   16
#define T0_  2048
__device__ float g_h   [B_*64 *T0_];   // conv_in out (= hold)
__device__ float g_xn  [B_*64 *T0_];   // rmsnorm out
__device__ float g_xz  [B_*256*T0_];   // in_proj out: ch 0..127 = xm, 128..255 = z
__device__ float g_xs  [B_*128*T0_];   // dwconv+silu out (u)
__device__ float g_xdbl[B_*36 *T0_];   // x_proj out: 0..3 dt, 4..19 B, 20..35 C
__device__ float g_dl  [B_*128*T0_];   // delta (softplus)
__device__ float g_y   [B_*128*T0_];   // scan out * silu(z)
__device__ float g_h2  [B_*64 *T0_];   // mamba out (+residual)
__device__ float g_mg  [B_*64 *T0_];   // merge conv raw
__device__ float g_m   [B_*64 *T0_];   // post-BN + hold
__device__ float g_u5  [B_*320*10240]; // up1 (shuffled)
__device__ float g_u10 [B_*128*20480]; // up2 (shuffled)
__device__ float g_stats[128];         // mean[64], rstd[64]

// ---------------- generic conv1d (cross-correlation), FFMA2, conflict-free ------
// Thread lane owns 4 t-pairs at t_local = lane*2 + j*64 (T_TILE=256).
// x tile kept in TWO smem copies: sx0[i]=x[i], sx1[i]=x[i+1], so any pair
// (x[s],x[s+1]) is ONE aligned LDS.64 (from sx0 if s even, sx1 if s odd).
// Weights stored duplicated as float2 with row stride KS (=16 for K=15) so two
// consecutive k-taps come back in ONE broadcast LDS.128 (ulonglong2), halving
// the weight-side smem crossbar traffic vs per-tap LDS.64.
constexpr int A_NONE = 0, A_LEAKY = 1, A_SOFTPLUS = 2;

template<int K, int PAD, int CG, int CPT, int R, int ACT, bool HAS_BIAS, bool HAS_RES, int MINB>
__global__ void __launch_bounds__(CG*32, MINB)
conv_kern(const float* __restrict__ in, const float* __restrict__ w,
          const float* __restrict__ bias, const float* __restrict__ res,
          float* __restrict__ out, int CI, int CO, int T, int inbs)
{
    constexpr int T_TILE  = 256;
    constexpr int CO_TILE = CG * CPT;
    constexpr int NT      = CG * 32;
    constexpr int XN      = T_TILE + K - 1;
    constexpr int XNP     = (XN + 4 + 3) & ~3;
    constexpr int NP      = K / 2;                 // full k-pairs
    constexpr int KS      = (NP > 0) ? ((K + 1) & ~1) : 1;  // padded weight row stride
    constexpr int WN      = CO_TILE * K;           // actual weights per ci
    constexpr int XE      = (XN + NT - 1) / NT;
    constexpr int WE      = (WN + NT - 1) / NT;

    __shared__ __align__(16) float  sx0[2][XNP];
    __shared__ __align__(16) float  sx1[2][XNP];
    __shared__ __align__(16) float2 sw [2][CO_TILE * KS];

    const int tid  = threadIdx.x;
    const int lane = tid & 31;
    const int cg   = tid >> 5;
    const int b    = blockIdx.z;
    const int t0   = blockIdx.x * T_TILE;
    const int co0  = blockIdx.y * CO_TILE;
    const float* inb = in + (long)b * inbs;

    float rx[XE], rw[WE];
    auto prefetch = [&](int ci) {
#pragma unroll
        for (int e = 0; e < XE; e++) {
            int idx = tid + e * NT;
            if (idx < XN) {
                int gt = t0 - PAD + idx;
                rx[e] = (gt >= 0 && gt < T) ? __ldg(inb + (long)ci * T + gt) : 0.f;
            }
        }
#pragma unroll
        for (int e = 0; e < WE; e++) {
            int idx = tid + e * NT;
            if (idx < WN) {
                int co = idx / K, k = idx % K;
                int gco = co0 + co;
                rw[e] = (gco < CO) ? __ldg(w + ((long)gco * CI + ci) * K + k) : 0.f;
            }
        }
    };
    auto store_buf = [&](int bf) {
#pragma unroll
        for (int e = 0; e < XE; e++) {
            int idx = tid + e * NT;
            if (idx < XN) {
                float v = rx[e];
                sx0[bf][idx] = v;
                if (idx > 0) sx1[bf][idx - 1] = v;
            }
        }
#pragma unroll
        for (int e = 0; e < WE; e++) {
            int idx = tid + e * NT;
            if (idx < WN) {
                int co = idx / K, k = idx % K;
                sw[bf][co * KS + k] = make_float2(rw[e], rw[e]);
            }
        }
    };

    u64 acc[CPT][4];
#pragma unroll
    for (int i = 0; i < CPT; i++) {
        int co = co0 + cg * CPT + i;
        float bv = (HAS_BIAS && co < CO) ? __ldg(bias + co) : 0.f;
        u64 p = pack2(bv, bv);
#pragma unroll
        for (int j = 0; j < 4; j++) acc[i][j] = p;
    }

    prefetch(0);
    store_buf(0);
    int bf = 0;
    for (int ci = 0; ci < CI; ci++) {
        __syncthreads();
        if (ci + 1 < CI) prefetch(ci + 1);

        const float2* swb = &sw[bf][cg * CPT * KS];
        const float*  x0b = &sx0[bf][lane * 2];
        const float*  x1b = &sx1[bf][lane * 2];

        // full k-pairs: even tap from sx0, odd tap from sx1, weights via LDS.128
#pragma unroll
        for (int kp = 0; kp < NP; kp++) {
            const int k0 = 2 * kp;
            u64 xva[4], xvb[4];
#pragma unroll
            for (int j = 0; j < 4; j++) {
                xva[j] = *(const u64*)(x0b + k0 + j * 64);
                xvb[j] = *(const u64*)(x1b + k0 + j * 64);
            }
#pragma unroll
            for (int i = 0; i < CPT; i++) {
                ulonglong2 wv = *(const ulonglong2*)(swb + i * KS + k0);
#pragma unroll
                for (int j = 0; j < 4; j++) acc[i][j] = fma2(wv.x, xva[j], acc[i][j]);
#pragma unroll
                for (int j = 0; j < 4; j++) acc[i][j] = fma2(wv.y, xvb[j], acc[i][j]);
            }
        }
        // odd-K tail tap (k = K-1, even index)
        if (K & 1) {
            const int kt = K - 1;
            u64 xv[4];
#pragma unroll
            for (int j = 0; j < 4; j++)
                xv[j] = *(const u64*)(x0b + kt + j * 64);
#pragma unroll
            for (int i = 0; i < CPT; i++) {
                u64 wd = *(const u64*)(swb + i * KS + kt);
#pragma unroll
                for (int j = 0; j < 4; j++) acc[i][j] = fma2(wd, xv[j], acc[i][j]);
            }
        }

        if (ci + 1 < CI) store_buf(bf ^ 1);
        bf ^= 1;
    }

    // epilogue: activation, optional residual, optional pixel-shuffle store
#pragma unroll
    for (int i = 0; i < CPT; i++) {
        int co = co0 + cg * CPT + i;
        if (co >= CO) continue;
#pragma unroll
        for (int j = 0; j < 4; j++) {
            float v0, v1; unpack2(acc[i][j], v0, v1);
            if (ACT == A_LEAKY) {
                v0 = v0 >= 0.f ? v0 : 0.01f * v0;
                v1 = v1 >= 0.f ? v1 : 0.01f * v1;
            } else if (ACT == A_SOFTPLUS) {
                v0 = v0 > 20.f ? v0 : log1pf(__expf(v0));
                v1 = v1 > 20.f ? v1 : log1pf(__expf(v1));
            }
            int t = t0 + lane * 2 + j * 64;
            if (R == 1) {
                long o = ((long)b * CO + co) * T + t;
                if (HAS_RES) {
                    float2 rv = *(const float2*)(res + o);
                    v0 += rv.x; v1 += rv.y;
                }
                *(float2*)(out + o) = make_float2(v0, v1);
            } else {
                int  C2 = CO / R;
                long T2 = (long)T * R;
                long o  = ((long)b * C2 + co / R) * T2 + (long)t * R + (co % R);
                out[o] = v0; out[o + R] = v1;
            }
        }
    }
}

// ---------------- rmsnorm over channel dim (64), layout (b,64,T) ----------------
__global__ void rms_kern(const float* __restrict__ x, const float* __restrict__ nw,
                         float* __restrict__ xn, int T)
{
    int b = blockIdx.y;
    int t = blockIdx.x * blockDim.x + threadIdx.x;
    const float* p = x + (long)b * 64 * T + t;
    float s = 0.f;
#pragma unroll
    for (int c = 0; c < 64; c++) { float v = p[(long)c * T]; s += v * v; }
    float r = rsqrtf(s * (1.f / 64.f) + 1e-5f);
    float* q = xn + (long)b * 64 * T + t;
#pragma unroll
    for (int c = 0; c < 64; c++) q[(long)c * T] = p[(long)c * T] * r * __ldg(nw + c);
}

// ---------------- causal depthwise conv (k=4) + silu ----------------------------
__global__ void dwconv_kern(const float* __restrict__ xz, const float* __restrict__ w,
                            const float* __restrict__ bias, float* __restrict__ xs, int T)
{
    int b = blockIdx.y;
    int d = threadIdx.x;              // 128
    int t0 = blockIdx.x * 32;
    const float* x = xz + ((long)b * 256 + d) * T;   // xm = channels 0..127
    float w0 = w[d*4+0], w1 = w[d*4+1], w2 = w[d*4+2], w3 = w[d*4+3], bb = bias[d];
    float a  = (t0 >= 3) ? x[t0-3] : 0.f;
    float c1 = (t0 >= 2) ? x[t0-2] : 0.f;
    float c2 = (t0 >= 1) ? x[t0-1] : 0.f;
    float* o = xs + ((long)b * 128 + d) * T;
#pragma unroll
    for (int i = 0; i < 32; i++) {
        float c3 = x[t0 + i];
        float v  = w0*a + w1*c1 + w2*c2 + w3*c3 + bb;
        o[t0 + i] = v * (1.f / (1.f + __expf(-v)));   // silu
        a = c1; c1 = c2; c2 = c3;
    }
}

// ---------------- selective scan (sequential over T), 1 block per batch ---------
__global__ void scan_kern(const float* __restrict__ u_, const float* __restrict__ dl_,
                          const float* __restrict__ xz, const float* __restrict__ xdbl,
                          const float* __restrict__ A_log, const float* __restrict__ Dv,
                          float* __restrict__ yout, int T)
{
    int b = blockIdx.x;
    int d = threadIdx.x;              // 128
    float A[16];
#pragma unroll
    for (int n = 0; n < 16; n++) A[n] = -expf(__ldg(A_log + d * 16 + n));
    float Dd = __ldg(Dv + d);
    const float* u  = u_  + ((long)b * 128 + d) * T;
    const float* dl = dl_ + ((long)b * 128 + d) * T;
    const float* z  = xz  + ((long)b * 256 + 128 + d) * T;
    const float* Bc = xdbl + ((long)b * 36 + 4)  * T;
    const float* Cc = xdbl + ((long)b * 36 + 20) * T;
    float* y = yout + ((long)b * 128 + d) * T;

    float h[16];
#pragma unroll
    for (int n = 0; n < 16; n++) h[n] = 0.f;

    for (int t = 0; t < T; t++) {
        float dt = dl[t], ut = u[t];
        float du = dt * ut;
        float acc = 0.f;
#pragma unroll
        for (int n = 0; n < 16; n++) {
            float dA = __expf(dt * A[n]);
            h[n] = h[n] * dA + du * __ldg(Bc + (long)n * T + t);
            acc += h[n] * __ldg(Cc + (long)n * T + t);
        }
        float yt = acc + ut * Dd;
        float zt = z[t];
        y[t] = yt * (zt * (1.f / (1.f + __expf(-zt))));
    }
}

// ---------------- batchnorm: training-mode stats + apply(+hold) -----------------
__global__ void bnstat_kern(const float* __restrict__ x, float* __restrict__ stats, int T)
{
    int c = blockIdx.x, tid = threadIdx.x;
    int N = 16 * T;
    float s = 0.f, s2 = 0.f;
    for (int i = tid; i < N; i += 256) {
        int b = i / T, t = i - b * T;
        float v = x[((long)b * 64 + c) * T + t];
        s += v; s2 += v * v;
    }
    __shared__ float rs[256], rq[256];
    rs[tid] = s; rq[tid] = s2;
    __syncthreads();
    for (int st = 128; st > 0; st >>= 1) {
        if (tid < st) { rs[tid] += rs[tid + st]; rq[tid] += rq[tid + st]; }
        __syncthreads();
    }
    if (tid == 0) {
        float mean = rs[0] / N;
        float var  = rq[0] / N - mean * mean;
        stats[c] = mean;
        stats[64 + c] = rsqrtf(var + 1e-5f);
    }
}

__global__ void bnapply_kern(const float* __restrict__ x, const float* __restrict__ stats,
                             const float* __restrict__ g, const float* __restrict__ bb,
                             const float* __restrict__ hold, float* __restrict__ m, int T)
{
    long idx = (long)blockIdx.x * blockDim.x + threadIdx.x;
    long tot = (long)16 * 64 * T;
    if (idx >= tot) return;
    int c = (int)((idx / T) % 64);
    m[idx] = (x[idx] - stats[c]) * stats[64 + c] * g[c] + bb[c] + hold[idx];
}

// ---------------- launch --------------------------------------------------------
extern "C" void kernel_launch(void* const* d_in, const int* in_sizes, int n_in,
                              void* d_out, int out_size)
{
    (void)in_sizes; (void)n_in; (void)out_size;
    const float* x         = (const float*)d_in[0];
    const float* conv_in_w = (const float*)d_in[1];
    const float* conv_in_b = (const float*)d_in[2];
    const float* norm_w    = (const float*)d_in[3];
    const float* in_proj_w = (const float*)d_in[4];
    const float* dwconv_w  = (const float*)d_in[5];
    const float* dwconv_b  = (const float*)d_in[6];
    const float* x_proj_w  = (const float*)d_in[7];
    const float* dt_proj_w = (const float*)d_in[8];
    const float* dt_proj_b = (const float*)d_in[9];
    const float* A_log     = (const float*)d_in[10];
    const float* Dv        = (const float*)d_in[11];
    const float* out_proj_w= (const float*)d_in[12];
    const float* merge_w   = (const float*)d_in[13];
    const float* merge_b   = (const float*)d_in[14];
    const float* bn_g      = (const float*)d_in[15];
    const float* bn_b      = (const float*)d_in[16];
    const float* up1_w     = (const float*)d_in[17];
    const float* up1_b     = (const float*)d_in[18];
    const float* up2_w     = (const float*)d_in[19];
    const float* up2_b     = (const float*)d_in[20];
    const float* out_w     = (const float*)d_in[21];
    const float* out_b     = (const float*)d_in[22];
    float* dout = (float*)d_out;

    float *ph, *pxn, *pxz, *pxs, *pxdbl, *pdl, *py, *ph2, *pmg, *pm, *pu5, *pu10, *pst;
    cudaGetSymbolAddress((void**)&ph,    g_h);
    cudaGetSymbolAddress((void**)&pxn,   g_xn);
    cudaGetSymbolAddress((void**)&pxz,   g_xz);
    cudaGetSymbolAddress((void**)&pxs,   g_xs);
    cudaGetSymbolAddress((void**)&pxdbl, g_xdbl);
    cudaGetSymbolAddress((void**)&pdl,   g_dl);
    cudaGetSymbolAddress((void**)&py,    g_y);
    cudaGetSymbolAddress((void**)&ph2,   g_h2);
    cudaGetSymbolAddress((void**)&pmg,   g_mg);
    cudaGetSymbolAddress((void**)&pm,    g_m);
    cudaGetSymbolAddress((void**)&pu5,   g_u5);
    cudaGetSymbolAddress((void**)&pu10,  g_u10);
    cudaGetSymbolAddress((void**)&pst,   g_stats);

    const int T = 2048;

    // 1. conv_in (12->64, k=15, pad 7) + leaky
    conv_kern<15,7,8,8,1,A_LEAKY,true,false,2>
        <<<dim3(8,1,16),256>>>(x, conv_in_w, conv_in_b, nullptr, ph, 12, 64, T, 12*T);
    // 2. rmsnorm
    rms_kern<<<dim3(T/256,16),256>>>(ph, norm_w, pxn, T);
    // 3. in_proj (64->256, k=1, no bias)
    conv_kern<1,0,8,8,1,A_NONE,false,false,2>
        <<<dim3(8,4,16),256>>>(pxn, in_proj_w, nullptr, nullptr, pxz, 64, 256, T, 64*T);
    // 4. depthwise causal conv + silu
    dwconv_kern<<<dim3(T/32,16),128>>>(pxz, dwconv_w, dwconv_b, pxs, T);
    // 5. x_proj (128->36, k=1, no bias)
    conv_kern<1,0,9,4,1,A_NONE,false,false,2>
        <<<dim3(8,1,16),288>>>(pxs, x_proj_w, nullptr, nullptr, pxdbl, 128, 36, T, 128*T);
    // 6. delta = softplus(dt @ dt_proj_w.T + b)  (4->128, k=1; input = dt rows of xdbl)
    conv_kern<1,0,16,8,1,A_SOFTPLUS,true,false,1>
        <<<dim3(8,1,16),512>>>(pxdbl, dt_proj_w, dt_proj_b, nullptr, pdl, 4, 128, T, 36*T);
    // 7. selective scan (+ D skip + silu(z) gate)
    scan_kern<<<16,128>>>(pxs, pdl, pxz, pxdbl, A_log, Dv, py, T);
    // 8. out_proj (128->64, k=1, no bias) + residual h
    conv_kern<1,0,8,8,1,A_NONE,false,true,2>
        <<<dim3(8,1,16),256>>>(py, out_proj_w, nullptr, ph, ph2, 128, 64, T, 128*T);
    // 9. merge conv (64->64, k=15, pad 7)
    conv_kern<15,7,8,8,1,A_NONE,true,false,2>
        <<<dim3(8,1,16),256>>>(ph2, merge_w, merge_b, nullptr, pmg, 64, 64, T, 64*T);
    // 10-11. batchnorm (training stats) + hold residual
    bnstat_kern<<<64,256>>>(pmg, pst, T);
    bnapply_kern<<<(16*64*T + 255)/256,256>>>(pmg, pst, bn_g, bn_b, ph, pm, T);
    // 12. up1 (64->1600, k=15) + pixel_shuffle r=5 + leaky -> (b,320,10240)
    conv_kern<15,7,8,8,5,A_LEAKY,true,false,2>
        <<<dim3(8,25,16),256>>>(pm, up1_w, up1_b, nullptr, pu5, 64, 1600, T, 64*T);
    // 13. up2 (320->256, k=15) + pixel_shuffle r=2 + leaky -> (b,128,20480)
    conv_kern<15,7,8,8,2,A_LEAKY,true,false,2>
        <<<dim3(40,4,16),256>>>(pu5, up2_w, up2_b, nullptr, pu10, 320, 256, 10240, 320*10240);
    // 14. out conv (128->12, k=15) -> d_out
    conv_kern<15,7,6,2,1,A_NONE,true,false,2>
        <<<dim3(80,1,16),192>>>(pu10, out_w, out_b, nullptr, dout, 128, 12, 20480, 128*20480);
}

// round 17
// speedup vs baseline: 2.3400x; 1.7530x over previous
#include <cuda_runtime.h>
#include <cuda_bf16.h>
#include <cstdint>

typedef unsigned long long u64;
#define DEV_INLINE __device__ __forceinline__

DEV_INLINE u64 pack2(float lo, float hi) {
    u64 r; asm("mov.b64 %0, {%1,%2};" : "=l"(r) : "f"(lo), "f"(hi)); return r;
}
DEV_INLINE void unpack2(u64 v, float& lo, float& hi) {
    asm("mov.b64 {%0,%1}, %2;" : "=f"(lo), "=f"(hi) : "l"(v));
}
DEV_INLINE u64 fma2(u64 a, u64 b, u64 c) {
    u64 d; asm("fma.rn.f32x2 %0, %1, %2, %3;" : "=l"(d) : "l"(a), "l"(b), "l"(c)); return d;
}
DEV_INLINE uint32_t smem_u32(const void* p) {
    uint32_t a;
    asm("{ .reg .u64 t; cvta.to.shared.u64 t, %1; cvt.u32.u64 %0, t; }" : "=r"(a) : "l"(p));
    return a;
}
// ---- Ampere-class async copy + warp MMA (portable PTX, no sm_103a features) ----
DEV_INLINE void cp16(uint32_t sa, const void* ga, int sz) {
    asm volatile("cp.async.ca.shared.global [%0], [%1], 16, %2;"
                 :: "r"(sa), "l"(ga), "r"(sz) : "memory");
}
#define CP_COMMIT() asm volatile("cp.async.commit_group;" ::: "memory")
#define CP_WAIT0()  asm volatile("cp.async.wait_group 0;" ::: "memory")
#define CP_WAIT1()  asm volatile("cp.async.wait_group 1;" ::: "memory")

DEV_INLINE void ldsm4(uint32_t* r, uint32_t a) {
    asm volatile("ldmatrix.sync.aligned.m8n8.x4.shared.b16 {%0,%1,%2,%3}, [%4];"
                 : "=r"(r[0]), "=r"(r[1]), "=r"(r[2]), "=r"(r[3]) : "r"(a));
}
DEV_INLINE void mma16816(float* c, const uint32_t* a, uint32_t b0, uint32_t b1) {
    asm volatile(
        "mma.sync.aligned.m16n8k16.row.col.f32.bf16.bf16.f32 "
        "{%0,%1,%2,%3}, {%4,%5,%6,%7}, {%8,%9}, {%0,%1,%2,%3};"
        : "+f"(c[0]), "+f"(c[1]), "+f"(c[2]), "+f"(c[3])
        : "r"(a[0]), "r"(a[1]), "r"(a[2]), "r"(a[3]), "r"(b0), "r"(b1));
}

// ---------------- scratch buffers (device globals; no allocation) ----------------
#define B_   16
#define T0_  2048
__device__ float g_h   [B_*64 *T0_];
__device__ float g_xn  [B_*64 *T0_];
__device__ float g_xz  [B_*256*T0_];
__device__ float g_xs  [B_*128*T0_];
__device__ float g_xdbl[B_*36 *T0_];
__device__ float g_dl  [B_*128*T0_];
__device__ float g_y   [B_*128*T0_];
__device__ float g_h2  [B_*64 *T0_];
__device__ float g_mg  [B_*64 *T0_];
__device__ float g_m   [B_*64 *T0_];
__device__ float g_u5  [B_*320*10240];
__device__ float g_u10 [B_*128*20480];
__device__ float g_stats[128];
// bf16 split operands for MMA convs
__device__ __nv_bfloat16 g_x1h[B_*2048*64],   g_x1l[B_*2048*64];     // up1 input^T
__device__ __nv_bfloat16 g_w1h[15*1664*64],   g_w1l[15*1664*64];     // up1 W (co pad 1664)
__device__ __nv_bfloat16 g_x2h[B_*10240*320], g_x2l[B_*10240*320];   // up2 input^T
__device__ __nv_bfloat16 g_w2h[15*256*320],   g_w2l[15*256*320];     // up2 W

// ---------------- generic conv1d, FFMA2 (small layers) --------------------------
constexpr int A_NONE = 0, A_LEAKY = 1, A_SOFTPLUS = 2;

template<int K, int PAD, int CG, int CPT, int R, int ACT, bool HAS_BIAS, bool HAS_RES, int MINB>
__global__ void __launch_bounds__(CG*32, MINB)
conv_kern(const float* __restrict__ in, const float* __restrict__ w,
          const float* __restrict__ bias, const float* __restrict__ res,
          float* __restrict__ out, int CI, int CO, int T, int inbs)
{
    constexpr int T_TILE  = 256;
    constexpr int CO_TILE = CG * CPT;
    constexpr int NT      = CG * 32;
    constexpr int XN      = T_TILE + K - 1;
    constexpr int XNP     = (XN + 4 + 3) & ~3;
    constexpr int NP      = K / 2;
    constexpr int KS      = (NP > 0) ? ((K + 1) & ~1) : 1;
    constexpr int WN      = CO_TILE * K;
    constexpr int XE      = (XN + NT - 1) / NT;
    constexpr int WE      = (WN + NT - 1) / NT;

    __shared__ __align__(16) float  sx0[2][XNP];
    __shared__ __align__(16) float  sx1[2][XNP];
    __shared__ __align__(16) float2 sw [2][CO_TILE * KS];

    const int tid  = threadIdx.x;
    const int lane = tid & 31;
    const int cg   = tid >> 5;
    const int b    = blockIdx.z;
    const int t0   = blockIdx.x * T_TILE;
    const int co0  = blockIdx.y * CO_TILE;
    const float* inb = in + (long)b * inbs;

    float rx[XE], rw[WE];
    auto prefetch = [&](int ci) {
#pragma unroll
        for (int e = 0; e < XE; e++) {
            int idx = tid + e * NT;
            if (idx < XN) {
                int gt = t0 - PAD + idx;
                rx[e] = (gt >= 0 && gt < T) ? __ldg(inb + (long)ci * T + gt) : 0.f;
            }
        }
#pragma unroll
        for (int e = 0; e < WE; e++) {
            int idx = tid + e * NT;
            if (idx < WN) {
                int co = idx / K, k = idx % K;
                int gco = co0 + co;
                rw[e] = (gco < CO) ? __ldg(w + ((long)gco * CI + ci) * K + k) : 0.f;
            }
        }
    };
    auto store_buf = [&](int bf) {
#pragma unroll
        for (int e = 0; e < XE; e++) {
            int idx = tid + e * NT;
            if (idx < XN) {
                float v = rx[e];
                sx0[bf][idx] = v;
                if (idx > 0) sx1[bf][idx - 1] = v;
            }
        }
#pragma unroll
        for (int e = 0; e < WE; e++) {
            int idx = tid + e * NT;
            if (idx < WN) {
                int co = idx / K, k = idx % K;
                sw[bf][co * KS + k] = make_float2(rw[e], rw[e]);
            }
        }
    };

    u64 acc[CPT][4];
#pragma unroll
    for (int i = 0; i < CPT; i++) {
        int co = co0 + cg * CPT + i;
        float bv = (HAS_BIAS && co < CO) ? __ldg(bias + co) : 0.f;
        u64 p = pack2(bv, bv);
#pragma unroll
        for (int j = 0; j < 4; j++) acc[i][j] = p;
    }

    prefetch(0);
    store_buf(0);
    int bf = 0;
    for (int ci = 0; ci < CI; ci++) {
        __syncthreads();
        if (ci + 1 < CI) prefetch(ci + 1);

        const float2* swb = &sw[bf][cg * CPT * KS];
        const float*  x0b = &sx0[bf][lane * 2];
        const float*  x1b = &sx1[bf][lane * 2];
#pragma unroll
        for (int kp = 0; kp < NP; kp++) {
            const int k0 = 2 * kp;
            u64 xva[4], xvb[4];
#pragma unroll
            for (int j = 0; j < 4; j++) {
                xva[j] = *(const u64*)(x0b + k0 + j * 64);
                xvb[j] = *(const u64*)(x1b + k0 + j * 64);
            }
#pragma unroll
            for (int i = 0; i < CPT; i++) {
                ulonglong2 wv = *(const ulonglong2*)(swb + i * KS + k0);
#pragma unroll
                for (int j = 0; j < 4; j++) acc[i][j] = fma2(wv.x, xva[j], acc[i][j]);
#pragma unroll
                for (int j = 0; j < 4; j++) acc[i][j] = fma2(wv.y, xvb[j], acc[i][j]);
            }
        }
        if (K & 1) {
            const int kt = K - 1;
            u64 xv[4];
#pragma unroll
            for (int j = 0; j < 4; j++)
                xv[j] = *(const u64*)(x0b + kt + j * 64);
#pragma unroll
            for (int i = 0; i < CPT; i++) {
                u64 wd = *(const u64*)(swb + i * KS + kt);
#pragma unroll
                for (int j = 0; j < 4; j++) acc[i][j] = fma2(wd, xv[j], acc[i][j]);
            }
        }
        if (ci + 1 < CI) store_buf(bf ^ 1);
        bf ^= 1;
    }

#pragma unroll
    for (int i = 0; i < CPT; i++) {
        int co = co0 + cg * CPT + i;
        if (co >= CO) continue;
#pragma unroll
        for (int j = 0; j < 4; j++) {
            float v0, v1; unpack2(acc[i][j], v0, v1);
            if (ACT == A_LEAKY) {
                v0 = v0 >= 0.f ? v0 : 0.01f * v0;
                v1 = v1 >= 0.f ? v1 : 0.01f * v1;
            } else if (ACT == A_SOFTPLUS) {
                v0 = v0 > 20.f ? v0 : log1pf(__expf(v0));
                v1 = v1 > 20.f ? v1 : log1pf(__expf(v1));
            }
            int t = t0 + lane * 2 + j * 64;
            if (R == 1) {
                long o = ((long)b * CO + co) * T + t;
                if (HAS_RES) {
                    float2 rv = *(const float2*)(res + o);
                    v0 += rv.x; v1 += rv.y;
                }
                *(float2*)(out + o) = make_float2(v0, v1);
            } else {
                int  C2 = CO / R;
                long T2 = (long)T * R;
                long o  = ((long)b * C2 + co / R) * T2 + (long)t * R + (co % R);
                out[o] = v0; out[o + R] = v1;
            }
        }
    }
}

// ---------------- bf16 split prep: weights (co,ci,15) -> [k][cop][ci] hi/lo -----
__global__ void prep_w_kern(const float* __restrict__ src, __nv_bfloat16* __restrict__ dh,
                            __nv_bfloat16* __restrict__ dl, int CO, int COP, int CI)
{
    long idx = (long)blockIdx.x * blockDim.x + threadIdx.x;
    long tot = (long)15 * COP * CI;
    if (idx >= tot) return;
    int k   = (int)(idx / ((long)COP * CI));
    long r  = idx - (long)k * COP * CI;
    int cop = (int)(r / CI);
    int ci  = (int)(r - (long)cop * CI);
    float v = (cop < CO) ? src[((long)cop * CI + ci) * 15 + k] : 0.f;
    __nv_bfloat16 h = __float2bfloat16(v);
    dh[idx] = h;
    dl[idx] = __float2bfloat16(v - __bfloat162float(h));
}

// ---------------- bf16 split prep: activations (b,CI,T) -> (b,T,CI) hi/lo -------
__global__ void prep_x_kern(const float* __restrict__ src, __nv_bfloat16* __restrict__ dh,
                            __nv_bfloat16* __restrict__ dl, int CI, int TS)
{
    __shared__ float tile[32][33];
    int b  = blockIdx.z;
    int t0 = blockIdx.x * 32, ci0 = blockIdx.y * 32;
    int tx = threadIdx.x, ty = threadIdx.y;
    for (int i = ty; i < 32; i += 8)
        tile[i][tx] = src[((long)b * CI + ci0 + i) * TS + t0 + tx];
    __syncthreads();
    for (int i = ty; i < 32; i += 8) {
        float v = tile[tx][i];
        __nv_bfloat16 h = __float2bfloat16(v);
        long o = ((long)b * TS + t0 + i) * CI + ci0 + tx;
        dh[o] = h;
        dl[o] = __float2bfloat16(v - __bfloat162float(h));
    }
}

// ---------------- HMMA implicit-GEMM conv (k=15, pad 7) + shuffle + leaky -------
// D[t, co] = sum_{k,ci} X^T[t+k-7, ci] * W_k[co, ci]; both K-major -> mma row.col.
// Block: 128 t x 128 co; 8 warps of 32t x 64co. Smem rows padded to 144B
// (9 x 16B -> ldmatrix chunk (9r+c) mod 8 conflict-free). cp.async double buffer.
// 3-pass bf16 split: Xh*Wh + Xh*Wl + Xl*Wh.
template<int TSRC, int CIC, int CO, int COP, int R>
__global__ void __launch_bounds__(256, 1)
mmaconv_kern(const __nv_bfloat16* __restrict__ wh, const __nv_bfloat16* __restrict__ wl,
             const __nv_bfloat16* __restrict__ xh, const __nv_bfloat16* __restrict__ xl,
             const float* __restrict__ bias, float* __restrict__ out)
{
    constexpr int CIW   = CIC * 64;
    constexpr int NS    = 15 * CIC;
    constexpr int CO2   = CO / R;
    constexpr long TOUT = (long)TSRC * R;
    constexpr int OPB   = 128 * 144;          // bytes per operand tile (128 rows x 144B)
    constexpr int STAGE = 4 * OPB;            // Xh, Xl, Wh, Wl

    extern __shared__ __align__(16) char dsm[];
    const uint32_t d32 = smem_u32(dsm);

    const int tid  = threadIdx.x;
    const int wid  = tid >> 5, lane = tid & 31;
    const int wm   = wid & 3;                 // warp t-row group (32 each)
    const int wn   = wid >> 2;                // warp co group (64 each)
    const int t0   = blockIdx.x * 128;
    const int co0  = blockIdx.y * 128;
    const int bz   = blockIdx.z;

    const int lrow = tid >> 1;                // 0..127
    const int half = tid & 1;                 // 64B half of a 128B row

    auto issue = [&](int s, int st) {
        const int k   = s / CIC;
        const int ci0 = (s - k * CIC) * 64;
        const uint32_t sbase = d32 + st * STAGE + lrow * 144 + half * 64;
        // X rows (t) with conv halo shift
        int trow = t0 + lrow + k - 7;
        const bool ok = (trow >= 0 && trow < TSRC);
        const int tc = ok ? trow : 0;
        const int sz = ok ? 16 : 0;
        const __nv_bfloat16* gxh = xh + ((long)bz * TSRC + tc) * CIW + ci0 + half * 32;
        const __nv_bfloat16* gxl = xl + ((long)bz * TSRC + tc) * CIW + ci0 + half * 32;
        // W rows (co) — COP is grid-exact, always in range
        const __nv_bfloat16* gwh = wh + ((long)k * COP + co0 + lrow) * CIW + ci0 + half * 32;
        const __nv_bfloat16* gwl = wl + ((long)k * COP + co0 + lrow) * CIW + ci0 + half * 32;
#pragma unroll
        for (int c = 0; c < 4; c++) {
            cp16(sbase + 0 * OPB + c * 16, gxh + c * 8, sz);
            cp16(sbase + 1 * OPB + c * 16, gxl + c * 8, sz);
            cp16(sbase + 2 * OPB + c * 16, gwh + c * 8, 16);
            cp16(sbase + 3 * OPB + c * 16, gwl + c * 8, 16);
        }
    };

    float acc[2][8][4];
#pragma unroll
    for (int mt = 0; mt < 2; mt++)
#pragma unroll
        for (int nt = 0; nt < 8; nt++)
#pragma unroll
            for (int j = 0; j < 4; j++) acc[mt][nt][j] = 0.f;

    // ldmatrix lane addressing
    const int arow = lane & 15;               // A: row within 16-row tile
    const int acol = (lane >> 4) * 16;        // A: k-half byte offset
    const int brow = (lane & 7) + ((lane >> 4) & 1) * 8;   // B: n row within 16
    const int bcol = ((lane >> 3) & 1) * 16;  // B: k-half byte offset

    issue(0, 0);
    CP_COMMIT();
    for (int s = 0; s < NS; s++) {
        const int st = s & 1;
        if (s + 1 < NS) { issue(s + 1, st ^ 1); CP_COMMIT(); CP_WAIT1(); }
        else            { CP_WAIT0(); }
        __syncthreads();

        const uint32_t xhb = d32 + st * STAGE + 0 * OPB;
        const uint32_t xlb = d32 + st * STAGE + 1 * OPB;
        const uint32_t whb = d32 + st * STAGE + 2 * OPB;
        const uint32_t wlb = d32 + st * STAGE + 3 * OPB;
#pragma unroll
        for (int kk = 0; kk < 4; kk++) {
            uint32_t ah[2][4], al[2][4], bh[4][4], bl[4][4];
#pragma unroll
            for (int mt = 0; mt < 2; mt++) {
                uint32_t ao = (wm * 32 + mt * 16 + arow) * 144 + kk * 32 + acol;
                ldsm4(ah[mt], xhb + ao);
                ldsm4(al[mt], xlb + ao);
            }
#pragma unroll
            for (int np = 0; np < 4; np++) {
                uint32_t bo = (wn * 64 + np * 16 + brow) * 144 + kk * 32 + bcol;
                ldsm4(bh[np], whb + bo);
                ldsm4(bl[np], wlb + bo);
            }
#pragma unroll
            for (int mt = 0; mt < 2; mt++)
#pragma unroll
                for (int np = 0; np < 4; np++) {
                    mma16816(acc[mt][2*np],   ah[mt], bh[np][0], bh[np][1]);
                    mma16816(acc[mt][2*np+1], ah[mt], bh[np][2], bh[np][3]);
                    mma16816(acc[mt][2*np],   ah[mt], bl[np][0], bl[np][1]);
                    mma16816(acc[mt][2*np+1], ah[mt], bl[np][2], bl[np][3]);
                    mma16816(acc[mt][2*np],   al[mt], bh[np][0], bh[np][1]);
                    mma16816(acc[mt][2*np+1], al[mt], bh[np][2], bh[np][3]);
                }
        }
        __syncthreads();   // all warps done reading stage st before it is overwritten
    }

    // epilogue: bias + leaky + pixel-shuffle store
#pragma unroll
    for (int mt = 0; mt < 2; mt++) {
        const int t = t0 + wm * 32 + mt * 16 + (lane >> 2);
#pragma unroll
        for (int nt = 0; nt < 8; nt++) {
            const int co = co0 + wn * 64 + nt * 8 + (lane & 3) * 2;
#pragma unroll
            for (int j = 0; j < 4; j++) {
                const int cc = co + (j & 1);
                if (cc >= CO) continue;
                const int tt = t + (j >> 1) * 8;
                float v = acc[mt][nt][j] + __ldg(bias + cc);
                v = v >= 0.f ? v : 0.01f * v;
                out[((long)bz * CO2 + cc / R) * TOUT + (long)tt * R + (cc % R)] = v;
            }
        }
    }
}

// ---------------- rmsnorm -------------------------------------------------------
__global__ void rms_kern(const float* __restrict__ x, const float* __restrict__ nw,
                         float* __restrict__ xn, int T)
{
    int b = blockIdx.y;
    int t = blockIdx.x * blockDim.x + threadIdx.x;
    const float* p = x + (long)b * 64 * T + t;
    float s = 0.f;
#pragma unroll
    for (int c = 0; c < 64; c++) { float v = p[(long)c * T]; s += v * v; }
    float r = rsqrtf(s * (1.f / 64.f) + 1e-5f);
    float* q = xn + (long)b * 64 * T + t;
#pragma unroll
    for (int c = 0; c < 64; c++) q[(long)c * T] = p[(long)c * T] * r * __ldg(nw + c);
}

// ---------------- causal depthwise conv (k=4) + silu ----------------------------
__global__ void dwconv_kern(const float* __restrict__ xz, const float* __restrict__ w,
                            const float* __restrict__ bias, float* __restrict__ xs, int T)
{
    int b = blockIdx.y;
    int d = threadIdx.x;
    int t0 = blockIdx.x * 32;
    const float* x = xz + ((long)b * 256 + d) * T;
    float w0 = w[d*4+0], w1 = w[d*4+1], w2 = w[d*4+2], w3 = w[d*4+3], bb = bias[d];
    float a  = (t0 >= 3) ? x[t0-3] : 0.f;
    float c1 = (t0 >= 2) ? x[t0-2] : 0.f;
    float c2 = (t0 >= 1) ? x[t0-1] : 0.f;
    float* o = xs + ((long)b * 128 + d) * T;
#pragma unroll
    for (int i = 0; i < 32; i++) {
        float c3 = x[t0 + i];
        float v  = w0*a + w1*c1 + w2*c2 + w3*c3 + bb;
        o[t0 + i] = v * (1.f / (1.f + __expf(-v)));
        a = c1; c1 = c2; c2 = c3;
    }
}

// ---------------- selective scan ------------------------------------------------
__global__ void scan_kern(const float* __restrict__ u_, const float* __restrict__ dl_,
                          const float* __restrict__ xz, const float* __restrict__ xdbl,
                          const float* __restrict__ A_log, const float* __restrict__ Dv,
                          float* __restrict__ yout, int T)
{
    int b = blockIdx.x;
    int d = threadIdx.x;
    float A[16];
#pragma unroll
    for (int n = 0; n < 16; n++) A[n] = -expf(__ldg(A_log + d * 16 + n));
    float Dd = __ldg(Dv + d);
    const float* u  = u_  + ((long)b * 128 + d) * T;
    const float* dl = dl_ + ((long)b * 128 + d) * T;
    const float* z  = xz  + ((long)b * 256 + 128 + d) * T;
    const float* Bc = xdbl + ((long)b * 36 + 4)  * T;
    const float* Cc = xdbl + ((long)b * 36 + 20) * T;
    float* y = yout + ((long)b * 128 + d) * T;

    float h[16];
#pragma unroll
    for (int n = 0; n < 16; n++) h[n] = 0.f;

    for (int t = 0; t < T; t++) {
        float dt = dl[t], ut = u[t];
        float du = dt * ut;
        float acc = 0.f;
#pragma unroll
        for (int n = 0; n < 16; n++) {
            float dA = __expf(dt * A[n]);
            h[n] = h[n] * dA + du * __ldg(Bc + (long)n * T + t);
            acc += h[n] * __ldg(Cc + (long)n * T + t);
        }
        float yt = acc + ut * Dd;
        float zt = z[t];
        y[t] = yt * (zt * (1.f / (1.f + __expf(-zt))));
    }
}

// ---------------- batchnorm -----------------------------------------------------
__global__ void bnstat_kern(const float* __restrict__ x, float* __restrict__ stats, int T)
{
    int c = blockIdx.x, tid = threadIdx.x;
    int N = 16 * T;
    float s = 0.f, s2 = 0.f;
    for (int i = tid; i < N; i += 256) {
        int b = i / T, t = i - b * T;
        float v = x[((long)b * 64 + c) * T + t];
        s += v; s2 += v * v;
    }
    __shared__ float rs[256], rq[256];
    rs[tid] = s; rq[tid] = s2;
    __syncthreads();
    for (int st = 128; st > 0; st >>= 1) {
        if (tid < st) { rs[tid] += rs[tid + st]; rq[tid] += rq[tid + st]; }
        __syncthreads();
    }
    if (tid == 0) {
        float mean = rs[0] / N;
        float var  = rq[0] / N - mean * mean;
        stats[c] = mean;
        stats[64 + c] = rsqrtf(var + 1e-5f);
    }
}

__global__ void bnapply_kern(const float* __restrict__ x, const float* __restrict__ stats,
                             const float* __restrict__ g, const float* __restrict__ bb,
                             const float* __restrict__ hold, float* __restrict__ m, int T)
{
    long idx = (long)blockIdx.x * blockDim.x + threadIdx.x;
    long tot = (long)16 * 64 * T;
    if (idx >= tot) return;
    int c = (int)((idx / T) % 64);
    m[idx] = (x[idx] - stats[c]) * stats[64 + c] * g[c] + bb[c] + hold[idx];
}

// ---------------- launch --------------------------------------------------------
extern "C" void kernel_launch(void* const* d_in, const int* in_sizes, int n_in,
                              void* d_out, int out_size)
{
    (void)in_sizes; (void)n_in; (void)out_size;
    const float* x         = (const float*)d_in[0];
    const float* conv_in_w = (const float*)d_in[1];
    const float* conv_in_b = (const float*)d_in[2];
    const float* norm_w    = (const float*)d_in[3];
    const float* in_proj_w = (const float*)d_in[4];
    const float* dwconv_w  = (const float*)d_in[5];
    const float* dwconv_b  = (const float*)d_in[6];
    const float* x_proj_w  = (const float*)d_in[7];
    const float* dt_proj_w = (const float*)d_in[8];
    const float* dt_proj_b = (const float*)d_in[9];
    const float* A_log     = (const float*)d_in[10];
    const float* Dv        = (const float*)d_in[11];
    const float* out_proj_w= (const float*)d_in[12];
    const float* merge_w   = (const float*)d_in[13];
    const float* merge_b   = (const float*)d_in[14];
    const float* bn_g      = (const float*)d_in[15];
    const float* bn_b      = (const float*)d_in[16];
    const float* up1_w     = (const float*)d_in[17];
    const float* up1_b     = (const float*)d_in[18];
    const float* up2_w     = (const float*)d_in[19];
    const float* up2_b     = (const float*)d_in[20];
    const float* out_w     = (const float*)d_in[21];
    const float* out_b     = (const float*)d_in[22];
    float* dout = (float*)d_out;

    float *ph, *pxn, *pxz, *pxs, *pxdbl, *pdl, *py, *ph2, *pmg, *pm, *pu5, *pu10, *pst;
    cudaGetSymbolAddress((void**)&ph,    g_h);
    cudaGetSymbolAddress((void**)&pxn,   g_xn);
    cudaGetSymbolAddress((void**)&pxz,   g_xz);
    cudaGetSymbolAddress((void**)&pxs,   g_xs);
    cudaGetSymbolAddress((void**)&pxdbl, g_xdbl);
    cudaGetSymbolAddress((void**)&pdl,   g_dl);
    cudaGetSymbolAddress((void**)&py,    g_y);
    cudaGetSymbolAddress((void**)&ph2,   g_h2);
    cudaGetSymbolAddress((void**)&pmg,   g_mg);
    cudaGetSymbolAddress((void**)&pm,    g_m);
    cudaGetSymbolAddress((void**)&pu5,   g_u5);
    cudaGetSymbolAddress((void**)&pu10,  g_u10);
    cudaGetSymbolAddress((void**)&pst,   g_stats);

    __nv_bfloat16 *px1h, *px1l, *pw1h, *pw1l, *px2h, *px2l, *pw2h, *pw2l;
    cudaGetSymbolAddress((void**)&px1h, g_x1h);
    cudaGetSymbolAddress((void**)&px1l, g_x1l);
    cudaGetSymbolAddress((void**)&pw1h, g_w1h);
    cudaGetSymbolAddress((void**)&pw1l, g_w1l);
    cudaGetSymbolAddress((void**)&px2h, g_x2h);
    cudaGetSymbolAddress((void**)&px2l, g_x2l);
    cudaGetSymbolAddress((void**)&pw2h, g_w2h);
    cudaGetSymbolAddress((void**)&pw2l, g_w2l);

    const int T = 2048;
    const int DSMEM = 2 * 4 * 128 * 144;   // 147456 bytes
    cudaFuncSetAttribute(mmaconv_kern<2048, 1, 1600, 1664, 5>,
                         cudaFuncAttributeMaxDynamicSharedMemorySize, DSMEM);
    cudaFuncSetAttribute(mmaconv_kern<10240, 5, 256, 256, 2>,
                         cudaFuncAttributeMaxDynamicSharedMemorySize, DSMEM);

    // 1. conv_in (12->64, k=15) + leaky
    conv_kern<15,7,8,8,1,A_LEAKY,true,false,2>
        <<<dim3(8,1,16),256>>>(x, conv_in_w, conv_in_b, nullptr, ph, 12, 64, T, 12*T);
    // 2. rmsnorm
    rms_kern<<<dim3(T/256,16),256>>>(ph, norm_w, pxn, T);
    // 3. in_proj (64->256)
    conv_kern<1,0,8,8,1,A_NONE,false,false,2>
        <<<dim3(8,4,16),256>>>(pxn, in_proj_w, nullptr, nullptr, pxz, 64, 256, T, 64*T);
    // 4. dwconv + silu
    dwconv_kern<<<dim3(T/32,16),128>>>(pxz, dwconv_w, dwconv_b, pxs, T);
    // 5. x_proj (128->36)
    conv_kern<1,0,9,4,1,A_NONE,false,false,2>
        <<<dim3(8,1,16),288>>>(pxs, x_proj_w, nullptr, nullptr, pxdbl, 128, 36, T, 128*T);
    // 6. delta (4->128, softplus)
    conv_kern<1,0,16,8,1,A_SOFTPLUS,true,false,1>
        <<<dim3(8,1,16),512>>>(pxdbl, dt_proj_w, dt_proj_b, nullptr, pdl, 4, 128, T, 36*T);
    // 7. selective scan
    scan_kern<<<16,128>>>(pxs, pdl, pxz, pxdbl, A_log, Dv, py, T);
    // 8. out_proj (128->64) + residual
    conv_kern<1,0,8,8,1,A_NONE,false,true,2>
        <<<dim3(8,1,16),256>>>(py, out_proj_w, nullptr, ph, ph2, 128, 64, T, 128*T);
    // 9. merge conv (64->64, k=15)
    conv_kern<15,7,8,8,1,A_NONE,true,false,2>
        <<<dim3(8,1,16),256>>>(ph2, merge_w, merge_b, nullptr, pmg, 64, 64, T, 64*T);
    // 10-11. batchnorm + hold
    bnstat_kern<<<64,256>>>(pmg, pst, T);
    bnapply_kern<<<(16*64*T + 255)/256,256>>>(pmg, pst, bn_g, bn_b, ph, pm, T);
    // 12. up1 via HMMA: prep splits, then implicit-GEMM (+shuffle r=5, leaky)
    prep_w_kern<<<(15*1664*64 + 255)/256,256>>>(up1_w, pw1h, pw1l, 1600, 1664, 64);
    prep_x_kern<<<dim3(2048/32, 64/32, 16),dim3(32,8)>>>(pm, px1h, px1l, 64, 2048);
    mmaconv_kern<2048, 1, 1600, 1664, 5>
        <<<dim3(16,13,16),256,DSMEM>>>(pw1h, pw1l, px1h, px1l, up1_b, pu5);
    // 13. up2 via HMMA (+shuffle r=2, leaky)
    prep_w_kern<<<(15*256*320 + 255)/256,256>>>(up2_w, pw2h, pw2l, 256, 256, 320);
    prep_x_kern<<<dim3(10240/32, 320/32, 16),dim3(32,8)>>>(pu5, px2h, px2l, 320, 10240);
    mmaconv_kern<10240, 5, 256, 256, 2>
        <<<dim3(80,2,16),256,DSMEM>>>(pw2h, pw2l, px2h, px2l, up2_b, pu10);
    // 14. out conv (128->12, k=15) -> d_out
    conv_kern<15,7,6,2,1,A_NONE,true,false,2>
        <<<dim3(80,1,16),192>>>(pu10, out_w, out_b, nullptr, dout, 128, 12, 20480, 128*20480);
}